// round 14
// baseline (speedup 1.0000x reference)
#include <cuda_runtime.h>
#include <cuda_bf16.h>
#include <cuda_fp16.h>
#include <cstdint>

// ---------------- constants ----------------
#define Bb   256
#define Pp   192
#define DD   768
#define EE   256
#define AA   8
#define KK   4

#define M_TOTAL   51712          // 256(ve) + 256(te) + 49152(pat) + 2048(att)
#define SEG1      256
#define SEG2      512
#define SEG3      49664
#define MTILES    404            // M_TOTAL / 128
#define BKC       64             // K per chunk (fp16 elems)
#define NCH       12             // 768 / 64

// SMEM: 2 operands (A, B), each 128 rows x 144 bytes, double buffered
#define ROWB    144
#define OPSZ    (128 * ROWB)     // 18432
#define OFF_A   0
#define OFF_B   (OPSZ)
#define STAGESZ (2 * OPSZ)       // 36864
#define DYNSZ   (2 * STAGESZ)    // 73728

// ---------------- scratch ----------------
__device__ __half g_pat[(size_t)Bb * Pp * EE];  // unnormalized patch embed (fp16)
__device__ __half g_att[(size_t)Bb * AA * EE];  // unnormalized att embed (fp16)
__device__ float g_sim[(size_t)Bb * AA * Pp];
__device__ __half g_wt[4][256 * 768];           // W^T fp16, [N][K]

// ---------------- PTX helpers ----------------
static __device__ __forceinline__ uint32_t smem_u32(const void* p) {
    uint32_t a;
    asm("{ .reg .u64 t; cvta.to.shared.u64 t, %1; cvt.u32.u64 %0, t; }"
        : "=r"(a) : "l"(p));
    return a;
}

#define LDSM4(r, addr) \
    asm volatile("ldmatrix.sync.aligned.m8n8.x4.shared.b16 {%0,%1,%2,%3}, [%4];" \
        : "=r"((r)[0]), "=r"((r)[1]), "=r"((r)[2]), "=r"((r)[3]) : "r"(addr))

#define MMA(c, a, b0, b1) \
    asm volatile("mma.sync.aligned.m16n8k16.row.col.f32.f16.f16.f32 " \
        "{%0,%1,%2,%3}, {%4,%5,%6,%7}, {%8,%9}, {%0,%1,%2,%3};" \
        : "+f"((c)[0]), "+f"((c)[1]), "+f"((c)[2]), "+f"((c)[3]) \
        : "r"((a)[0]), "r"((a)[1]), "r"((a)[2]), "r"((a)[3]), "r"(b0), "r"(b1))

static __device__ __forceinline__ void cp16(uint32_t s, const void* g) {
    asm volatile("cp.async.cg.shared.global [%0], [%1], 16;" :: "r"(s), "l"(g));
}
#define CP_COMMIT() asm volatile("cp.async.commit_group;" ::: "memory")
#define CP_WAIT0()  asm volatile("cp.async.wait_group 0;" ::: "memory")

// redux with memory clobber: warp-synchronizing + orders shared-mem writes
static __device__ __forceinline__ uint32_t redux_min(uint32_t v) {
    uint32_t d;
    asm volatile("redux.sync.min.u32 %0, %1, 0xFFFFFFFF;" : "=r"(d) : "r"(v) : "memory");
    return d;
}
static __device__ __forceinline__ uint32_t fkey(float f) {
    const uint32_t u = __float_as_uint(f);
    return (u & 0x80000000u) ? ~u : (u | 0x80000000u);
}
static __device__ __forceinline__ float funkey(uint32_t k) {
    const uint32_t u = (k & 0x80000000u) ? (k ^ 0x80000000u) : ~k;
    return __uint_as_float(u);
}

// ---------------- W transpose + fp16 convert ----------------
__global__ void wsplit_kernel(const float* __restrict__ W0, const float* __restrict__ W1,
                              const float* __restrict__ W2, const float* __restrict__ W3)
{
    const int z = blockIdx.z;
    const float* W = (z == 0) ? W0 : (z == 1) ? W1 : (z == 2) ? W2 : W3;
    __shared__ float tile[32][33];
    const int tx = threadIdx.x, ty = threadIdx.y;
    const int k0 = blockIdx.x * 32, n0 = blockIdx.y * 32;
#pragma unroll
    for (int i = 0; i < 4; i++)
        tile[ty + 8 * i][tx] = W[(size_t)(k0 + ty + 8 * i) * 256 + n0 + tx];
    __syncthreads();
#pragma unroll
    for (int i = 0; i < 4; i++) {
        const float v = tile[tx][ty + 8 * i];
        g_wt[z][(size_t)(n0 + ty + 8 * i) * 768 + k0 + tx] = __float2half(v);
    }
}

// ---------------- A convert+store helper (fp32 -> fp16) ----------------
static __device__ __forceinline__ void store_a(char* st, const float4* aReg,
                                               int arow, int t)
{
#pragma unroll
    for (int p = 0; p < 8; p++) {
        const float4 v = aReg[p];
        __half2 hp0 = __floats2half2_rn(v.x, v.y);
        __half2 hp1 = __floats2half2_rn(v.z, v.w);
        uint2 hv;
        hv.x = *(uint32_t*)&hp0; hv.y = *(uint32_t*)&hp1;
        const int byo = (p * 16 + arow) * ROWB + (t & 15) * 8;
        *(uint2*)(st + OFF_A + byo) = hv;
    }
}

// ---------------- fused HMMA GEMM: C[m,256] = A[m,768] @ W + bias ----------
__global__ __launch_bounds__(256, 2)
void gemm_mma(const float* __restrict__ vf, const float* __restrict__ tf,
              const float* __restrict__ af,
              const float* __restrict__ bv, const float* __restrict__ bt,
              const float* __restrict__ bp, const float* __restrict__ ba,
              float* __restrict__ out)
{
    extern __shared__ char dynsm[];
    __shared__ int sRowOff[128];

    const int t = threadIdx.x;
    const int warp = t >> 5;
    const int lane = t & 31;
    const int m0 = blockIdx.y * 128;
    const int bn = blockIdx.x;           // 0 or 1 (N halves) — adjacent CTAs share A via L2

    const int seg = (m0 < SEG1) ? 0 : (m0 < SEG2) ? 1 : (m0 < SEG3) ? 2 : 3;
    const float* Abase = (seg == 0 || seg == 2) ? vf : (seg == 1 ? tf : af);
    const float* bias = (seg == 0) ? bv : (seg == 1) ? bt : (seg == 2) ? bp : ba;
    const __half* wt = g_wt[seg];

    float* dstf = nullptr;
    __half* dsth = nullptr;
    int mrel;
    if (seg == 0)      { dstf = out;            mrel = m0; }
    else if (seg == 1) { dstf = out + Bb * EE;  mrel = m0 - SEG1; }
    else if (seg == 2) { dsth = g_pat;          mrel = m0 - SEG2; }
    else               { dsth = g_att;          mrel = m0 - SEG3; }

    if (t < 128) {
        const int m = m0 + t;
        int off;
        if (m < SEG1)        off = m * (193 * 768);
        else if (m < SEG2)   off = (m - SEG1) * 768;
        else if (m < SEG3) { const int mm = m - SEG2;
                             off = ((mm / 192) * 193 + 1 + (mm % 192)) * 768; }
        else                 off = (m - SEG3) * 768;
        sRowOff[t] = off;
    }
    __syncthreads();

    const uint32_t smem_u = smem_u32(dynsm);
    const int warp_m = warp & 1;          // 2 m-warps (64 rows each)
    const int warp_n = warp >> 1;         // 4 n-warps (32 cols each)
    const int g = lane >> 3, lr = lane & 7;
    const uint32_t aoff = (uint32_t)((warp_m * 64 + (g & 1) * 8 + lr) * ROWB + (g >> 1) * 16);
    const uint32_t boff = (uint32_t)((warp_n * 32 + (g & 1) * 8 + lr) * ROWB + (g >> 1) * 16);

    const int arow = t >> 4;              // 0..15, + 16*pass
    const int acol = (t & 15) * 4;        // floats
    const int brow = t >> 3;              // 0..31, + 32*pass
    const int bseg = (t & 7) * 16;        // bytes within 128B row

    float acc[4][4][4] = {};
    float4 aReg[8];

    // ---- prologue: stage 0 ----
#pragma unroll
    for (int p = 0; p < 8; p++)
        aReg[p] = *(const float4*)(Abase + sRowOff[p * 16 + arow] + acol);
#pragma unroll
    for (int q = 0; q < 4; q++) {
        const int row = brow + q * 32;
        const size_t gb = (size_t)(bn * 128 + row) * 1536 + bseg;
        cp16(smem_u + (uint32_t)(row * ROWB + bseg) + OFF_B, (const char*)wt + gb);
    }
    CP_COMMIT();
    store_a(dynsm, aReg, arow, t);
    CP_WAIT0();
    __syncthreads();

    // ---- main loop ----
    for (int c = 0; c < NCH; c++) {
        const int cur = c & 1;
        const int nxt = cur ^ 1;
        if (c + 1 < NCH) {
            const int kc = (c + 1) * BKC;
#pragma unroll
            for (int p = 0; p < 8; p++)
                aReg[p] = *(const float4*)(Abase + sRowOff[p * 16 + arow] + kc + acol);
            const uint32_t stb = smem_u + nxt * STAGESZ;
#pragma unroll
            for (int q = 0; q < 4; q++) {
                const int row = brow + q * 32;
                const size_t gb = (size_t)(bn * 128 + row) * 1536 + kc * 2 + bseg;
                cp16(stb + (uint32_t)(row * ROWB + bseg) + OFF_B, (const char*)wt + gb);
            }
            CP_COMMIT();
        }

        const uint32_t sb = smem_u + cur * STAGESZ;
#pragma unroll
        for (int ks = 0; ks < 4; ks++) {
            uint32_t ah[4][4], bb[2][4];
#pragma unroll
            for (int mt = 0; mt < 4; mt++)
                LDSM4(ah[mt], sb + OFF_A + aoff + mt * (16 * ROWB) + ks * 32);
#pragma unroll
            for (int n2 = 0; n2 < 2; n2++)
                LDSM4(bb[n2], sb + OFF_B + boff + n2 * (16 * ROWB) + ks * 32);
#pragma unroll
            for (int mt = 0; mt < 4; mt++)
#pragma unroll
                for (int nt = 0; nt < 4; nt++) {
                    float* cc = acc[mt][nt];
                    const int n2 = nt >> 1, no = nt & 1;
                    MMA(cc, ah[mt], bb[n2][no], bb[n2][2 + no]);
                }
        }

        if (c + 1 < NCH) {
            store_a(dynsm + nxt * STAGESZ, aReg, arow, t);
            CP_WAIT0();
        }
        __syncthreads();
    }

    // ---- epilogue: bias add + store (fp32 for ve/te, fp16 for pat/att) ----
    const int r0 = lane >> 2;
    const int cp2 = (lane & 3) * 2;
#pragma unroll
    for (int nt = 0; nt < 4; nt++) {
        const int gcol = bn * 128 + warp_n * 32 + nt * 8 + cp2;
        const float2 bb = *(const float2*)(bias + gcol);
#pragma unroll
        for (int mt = 0; mt < 4; mt++) {
            const int row0 = mrel + warp_m * 64 + mt * 16 + r0;
            const float x0 = acc[mt][nt][0] + bb.x, y0 = acc[mt][nt][1] + bb.y;
            const float x1 = acc[mt][nt][2] + bb.x, y1 = acc[mt][nt][3] + bb.y;
            if (dstf) {
                *(float2*)(dstf + (size_t)row0 * EE + gcol) = make_float2(x0, y0);
                *(float2*)(dstf + (size_t)(row0 + 8) * EE + gcol) = make_float2(x1, y1);
            } else {
                __half2 h0 = __floats2half2_rn(x0, y0);
                __half2 h1 = __floats2half2_rn(x1, y1);
                *(__half2*)(dsth + (size_t)row0 * EE + gcol) = h0;
                *(__half2*)(dsth + (size_t)(row0 + 8) * EE + gcol) = h1;
            }
        }
    }
}

// ---------------- sim v5: 4 patches/warp-iter, 8-lane group reduce ---------
__global__ __launch_bounds__(256)
void sim_kernel(const __half* __restrict__ pat, const __half* __restrict__ att,
                float* __restrict__ sim)
{
    __shared__ float s_att[AA][EE];
    const int b = blockIdx.x;
    const int t = threadIdx.x;
    const int warp = t >> 5, lane = t & 31;

    // warp w normalizes att row w into SMEM
    {
        const __half* ar = att + ((size_t)b * AA + warp) * EE;
        float v[8];
        float ss = 0.f;
#pragma unroll
        for (int i = 0; i < 8; i++) {
            v[i] = __half2float(ar[lane + 32 * i]);
            ss += v[i] * v[i];
        }
#pragma unroll
        for (int o = 16; o; o >>= 1) ss += __shfl_xor_sync(0xffffffffu, ss, o);
        const float inv = 1.f / fmaxf(sqrtf(ss), 1e-12f);
#pragma unroll
        for (int i = 0; i < 8; i++) s_att[warp][lane + 32 * i] = v[i] * inv;
    }
    __syncthreads();

    // warp handles 24 patches, 4 at a time; lane = (p-sub, e-lane)
    const int sub = lane >> 3;          // 0..3: which of the 4 patches
    const int el = lane & 7;            // 0..7: e-lane within patch
    for (int it = 0; it < 6; it++) {
        const int p = warp * 24 + it * 4 + sub;
        const __half* pr = pat + ((size_t)b * Pp + p) * EE;

        float acc[AA] = {};
        float ss = 0.f;
#pragma unroll
        for (int k = 0; k < 8; k++) {
            const int e0 = el * 4 + 32 * k;
            const uint2 q = *(const uint2*)(pr + e0);
            const __half2 h0 = *reinterpret_cast<const __half2*>(&q.x);
            const __half2 h1 = *reinterpret_cast<const __half2*>(&q.y);
            const float2 f0 = __half22float2(h0);
            const float2 f1 = __half22float2(h1);
            ss += f0.x * f0.x + f0.y * f0.y + f1.x * f1.x + f1.y * f1.y;
#pragma unroll
            for (int a = 0; a < AA; a++)
                acc[a] += f0.x * s_att[a][e0] + f0.y * s_att[a][e0 + 1]
                        + f1.x * s_att[a][e0 + 2] + f1.y * s_att[a][e0 + 3];
        }
        // reduce over the 8-lane group (xor 4,2,1 stays in group)
#pragma unroll
        for (int o = 4; o; o >>= 1) {
            ss += __shfl_xor_sync(0xffffffffu, ss, o);
#pragma unroll
            for (int a = 0; a < AA; a++)
                acc[a] += __shfl_xor_sync(0xffffffffu, acc[a], o);
        }
        if (el == 0) {
            const float inv = 1.f / fmaxf(sqrtf(ss), 1e-12f);
#pragma unroll
            for (int a = 0; a < AA; a++)
                sim[((size_t)b * AA + a) * Pp + p] = acc[a] * inv;
        }
    }
}

// ---------------- Hungarian v5c: branchless, register u, minimal syncs -----
#define HW 4
__global__ __launch_bounds__(32 * HW)
void hungarian_kernel(const float* __restrict__ simg, float* __restrict__ out)
{
    __shared__ float cost_s[HW][AA][Pp];
    __shared__ int   p_s[HW][Pp + 1];
    __shared__ short way_s[HW][Pp + 1];

    const int w = threadIdx.x >> 5;
    const int lane = threadIdx.x & 31;
    const int b = blockIdx.x * HW + w;
    const float FINF = 1e30f;

    float (*cost)[Pp] = cost_s[w];
    int*   psh = p_s[w];
    short* way = way_s[w];

    for (int idx = lane; idx < AA * Pp; idx += 32)
        cost[idx / Pp][idx % Pp] = -simg[(size_t)b * AA * Pp + idx];

    float total = 0.f;

    for (int round = 0; round < KK; round++) {
        float v[6];
#pragma unroll
        for (int s = 0; s < 6; s++) v[s] = 0.f;
        for (int j = lane; j <= Pp; j += 32) psh[j] = 0;
        float u_own = 0.f;                 // lane r owns u[r] (rows 1..8)
        __syncwarp();

        for (int i = 1; i <= AA; i++) {
            float minv[6];
            unsigned usedm = 0;
            unsigned visited = 0;
#pragma unroll
            for (int s = 0; s < 6; s++) minv[s] = FINF;

            int j0 = 0;
            int i0 = i;                    // conceptual p[0] = i
            while (true) {
                // mark incoming column j0 used (branchless; no-op for j0==0)
                {
                    const int cidx = j0 - 1;
                    const bool own = (j0 != 0) & ((cidx & 31) == lane);
                    usedm |= own ? (1u << (cidx >> 5)) : 0u;
                }
                visited |= (1u << i0);
                const float ui0 = __shfl_sync(0xffffffffu, u_own, i0);
                const float* crow = cost[i0 - 1];

                float best = FINF;
                int bestj = 1 << 20;
#pragma unroll
                for (int s = 0; s < 6; s++) {
                    const int c = s * 32 + lane;
                    const float cur = crow[c] - ui0 - v[s];
                    const bool freecol = !((usedm >> s) & 1);
                    const bool upd = freecol & (cur < minv[s]);
                    if (upd) way[c + 1] = (short)j0;       // predicated STS
                    minv[s] = upd ? cur : minv[s];
                    const float mv = freecol ? minv[s] : FINF;
                    if (mv < best) { best = mv; bestj = c + 1; }
                }
                const uint32_t mykey = fkey(best);
                const uint32_t gkey = redux_min(mykey);
                const float delta = funkey(gkey);

                // u update for visited rows (lane r owns u[r]) — branchless
                u_own += ((visited >> lane) & 1) ? delta : 0.f;
#pragma unroll
                for (int s = 0; s < 6; s++) {
                    const bool usedc = (usedm >> s) & 1;
                    v[s]    -= usedc ? delta : 0.f;
                    minv[s] -= usedc ? 0.f : delta;
                }
                const uint32_t idxc = (mykey == gkey) ? (uint32_t)bestj : 0xFFFFFFFFu;
                const int j1 = (int)redux_min(idxc);   // warp-sync: orders way[] stores
                i0 = psh[j1];                          // next matched row (0 = free col)
                j0 = j1;
                if (i0 == 0) break;
            }
            // redux above is the sync point: way[] writes visible to lane 0;
            // lane 0's psh writes become visible at the next redux before any read.
            if (lane == 0) {
                int jc = j0;
                while (jc) {
                    const int jn = way[jc];
                    psh[jc] = (jn == 0) ? i : psh[jn];   // path root is row i
                    jc = jn;
                }
            }
        }
        __syncwarp();

        // collect matched values + mask
#pragma unroll
        for (int s = 0; s < 6; s++) {
            const int c = s * 32 + lane;
            const int r = psh[c + 1];
            if (r) {
                total += -cost[r - 1][c];
                cost[r - 1][c] = 100.f;
            }
        }
        __syncwarp();
    }

#pragma unroll
    for (int o = 16; o; o >>= 1) total += __shfl_xor_sync(0xffffffffu, total, o);
    if (lane == 0) out[b] = total * (1.f / (KK * AA));
}

// ---------------- launch ----------------
extern "C" void kernel_launch(void* const* d_in, const int* in_sizes, int n_in,
                              void* d_out, int out_size)
{
    const float* vf = (const float*)d_in[0];
    const float* tf = (const float*)d_in[1];
    const float* af = (const float*)d_in[2];
    const float* Wv = (const float*)d_in[4];
    const float* bv = (const float*)d_in[5];
    const float* Wt = (const float*)d_in[6];
    const float* bt = (const float*)d_in[7];
    const float* Wp = (const float*)d_in[8];
    const float* bp = (const float*)d_in[9];
    const float* Wa = (const float*)d_in[10];
    const float* ba = (const float*)d_in[11];

    float* out = (float*)d_out;
    float* ls = out + 2 * Bb * EE;

    __half *gpat, *gatt;
    float *gsim;
    cudaGetSymbolAddress((void**)&gpat, g_pat);
    cudaGetSymbolAddress((void**)&gatt, g_att);
    cudaGetSymbolAddress((void**)&gsim, g_sim);

    cudaFuncSetAttribute(gemm_mma, cudaFuncAttributeMaxDynamicSharedMemorySize, DYNSZ);

    wsplit_kernel<<<dim3(24, 8, 4), dim3(32, 8)>>>(Wv, Wt, Wp, Wa);
    gemm_mma<<<dim3(2, MTILES), 256, DYNSZ>>>(vf, tf, af, bv, bt, bp, ba, out);
    sim_kernel<<<Bb, 256>>>(gpat, gatt, gsim);
    hungarian_kernel<<<Bb / HW, 32 * HW>>>(gsim, ls);
}

// round 15
// speedup vs baseline: 1.1092x; 1.1092x over previous
#include <cuda_runtime.h>
#include <cuda_bf16.h>
#include <cuda_fp16.h>
#include <cstdint>

// ---------------- constants ----------------
#define Bb   256
#define Pp   192
#define DD   768
#define EE   256
#define AA   8
#define KK   4

#define M_TOTAL   51712          // 256(ve) + 256(te) + 49152(pat) + 2048(att)
#define SEG1      256
#define SEG2      512
#define SEG3      49664
#define MTILES    404            // M_TOTAL / 128
#define BKC       64             // K per chunk (fp16 elems)
#define NCH       12             // 768 / 64

// SMEM: 2 operands (A, B), each 128 rows x 144 bytes, double buffered
#define ROWB    144
#define OPSZ    (128 * ROWB)     // 18432
#define OFF_A   0
#define OFF_B   (OPSZ)
#define STAGESZ (2 * OPSZ)       // 36864
#define DYNSZ   (2 * STAGESZ)    // 73728

// ---------------- scratch ----------------
__device__ __half g_pat[(size_t)Bb * Pp * EE];  // unnormalized patch embed (fp16)
__device__ __half g_att[(size_t)Bb * AA * EE];  // unnormalized att embed (fp16)
__device__ float g_sim[(size_t)Bb * AA * Pp];
__device__ __half g_wt[4][256 * 768];           // W^T fp16, [N][K]

// ---------------- PTX helpers ----------------
static __device__ __forceinline__ uint32_t smem_u32(const void* p) {
    uint32_t a;
    asm("{ .reg .u64 t; cvta.to.shared.u64 t, %1; cvt.u32.u64 %0, t; }"
        : "=r"(a) : "l"(p));
    return a;
}

#define LDSM4(r, addr) \
    asm volatile("ldmatrix.sync.aligned.m8n8.x4.shared.b16 {%0,%1,%2,%3}, [%4];" \
        : "=r"((r)[0]), "=r"((r)[1]), "=r"((r)[2]), "=r"((r)[3]) : "r"(addr))

#define MMA(c, a, b0, b1) \
    asm volatile("mma.sync.aligned.m16n8k16.row.col.f32.f16.f16.f32 " \
        "{%0,%1,%2,%3}, {%4,%5,%6,%7}, {%8,%9}, {%0,%1,%2,%3};" \
        : "+f"((c)[0]), "+f"((c)[1]), "+f"((c)[2]), "+f"((c)[3]) \
        : "r"((a)[0]), "r"((a)[1]), "r"((a)[2]), "r"((a)[3]), "r"(b0), "r"(b1))

static __device__ __forceinline__ void cp16(uint32_t s, const void* g) {
    asm volatile("cp.async.cg.shared.global [%0], [%1], 16;" :: "r"(s), "l"(g));
}
#define CP_COMMIT() asm volatile("cp.async.commit_group;" ::: "memory")
#define CP_WAIT0()  asm volatile("cp.async.wait_group 0;" ::: "memory")

// redux with memory clobber: warp-synchronizing + orders shared-mem writes
static __device__ __forceinline__ uint32_t redux_min(uint32_t v) {
    uint32_t d;
    asm volatile("redux.sync.min.u32 %0, %1, 0xFFFFFFFF;" : "=r"(d) : "r"(v) : "memory");
    return d;
}
static __device__ __forceinline__ uint32_t fkey(float f) {
    const uint32_t u = __float_as_uint(f);
    return (u & 0x80000000u) ? ~u : (u | 0x80000000u);
}
static __device__ __forceinline__ float funkey(uint32_t k) {
    const uint32_t u = (k & 0x80000000u) ? (k ^ 0x80000000u) : ~k;
    return __uint_as_float(u);
}

// ---------------- W transpose + fp16 convert ----------------
__global__ void wsplit_kernel(const float* __restrict__ W0, const float* __restrict__ W1,
                              const float* __restrict__ W2, const float* __restrict__ W3)
{
    const int z = blockIdx.z;
    const float* W = (z == 0) ? W0 : (z == 1) ? W1 : (z == 2) ? W2 : W3;
    __shared__ float tile[32][33];
    const int tx = threadIdx.x, ty = threadIdx.y;
    const int k0 = blockIdx.x * 32, n0 = blockIdx.y * 32;
#pragma unroll
    for (int i = 0; i < 4; i++)
        tile[ty + 8 * i][tx] = W[(size_t)(k0 + ty + 8 * i) * 256 + n0 + tx];
    __syncthreads();
#pragma unroll
    for (int i = 0; i < 4; i++) {
        const float v = tile[tx][ty + 8 * i];
        g_wt[z][(size_t)(n0 + ty + 8 * i) * 768 + k0 + tx] = __float2half(v);
    }
}

// ---------------- A convert+store helper (fp32 -> fp16) ----------------
static __device__ __forceinline__ void store_a(char* st, const float4* aReg,
                                               int arow, int t)
{
#pragma unroll
    for (int p = 0; p < 8; p++) {
        const float4 v = aReg[p];
        __half2 hp0 = __floats2half2_rn(v.x, v.y);
        __half2 hp1 = __floats2half2_rn(v.z, v.w);
        uint2 hv;
        hv.x = *(uint32_t*)&hp0; hv.y = *(uint32_t*)&hp1;
        const int byo = (p * 16 + arow) * ROWB + (t & 15) * 8;
        *(uint2*)(st + OFF_A + byo) = hv;
    }
}

// ---------------- fused HMMA GEMM: C[m,256] = A[m,768] @ W + bias ----------
__global__ __launch_bounds__(256, 2)
void gemm_mma(const float* __restrict__ vf, const float* __restrict__ tf,
              const float* __restrict__ af,
              const float* __restrict__ bv, const float* __restrict__ bt,
              const float* __restrict__ bp, const float* __restrict__ ba,
              float* __restrict__ out)
{
    extern __shared__ char dynsm[];
    __shared__ int sRowOff[128];

    const int t = threadIdx.x;
    const int warp = t >> 5;
    const int lane = t & 31;
    const int m0 = blockIdx.y * 128;
    const int bn = blockIdx.x;           // 0 or 1 (N halves) — adjacent CTAs share A via L2

    const int seg = (m0 < SEG1) ? 0 : (m0 < SEG2) ? 1 : (m0 < SEG3) ? 2 : 3;
    const float* Abase = (seg == 0 || seg == 2) ? vf : (seg == 1 ? tf : af);
    const float* bias = (seg == 0) ? bv : (seg == 1) ? bt : (seg == 2) ? bp : ba;
    const __half* wt = g_wt[seg];

    float* dstf = nullptr;
    __half* dsth = nullptr;
    int mrel;
    if (seg == 0)      { dstf = out;            mrel = m0; }
    else if (seg == 1) { dstf = out + Bb * EE;  mrel = m0 - SEG1; }
    else if (seg == 2) { dsth = g_pat;          mrel = m0 - SEG2; }
    else               { dsth = g_att;          mrel = m0 - SEG3; }

    if (t < 128) {
        const int m = m0 + t;
        int off;
        if (m < SEG1)        off = m * (193 * 768);
        else if (m < SEG2)   off = (m - SEG1) * 768;
        else if (m < SEG3) { const int mm = m - SEG2;
                             off = ((mm / 192) * 193 + 1 + (mm % 192)) * 768; }
        else                 off = (m - SEG3) * 768;
        sRowOff[t] = off;
    }
    __syncthreads();

    const uint32_t smem_u = smem_u32(dynsm);
    const int warp_m = warp & 1;          // 2 m-warps (64 rows each)
    const int warp_n = warp >> 1;         // 4 n-warps (32 cols each)
    const int g = lane >> 3, lr = lane & 7;
    const uint32_t aoff = (uint32_t)((warp_m * 64 + (g & 1) * 8 + lr) * ROWB + (g >> 1) * 16);
    const uint32_t boff = (uint32_t)((warp_n * 32 + (g & 1) * 8 + lr) * ROWB + (g >> 1) * 16);

    const int arow = t >> 4;              // 0..15, + 16*pass
    const int acol = (t & 15) * 4;        // floats
    const int brow = t >> 3;              // 0..31, + 32*pass
    const int bseg = (t & 7) * 16;        // bytes within 128B row

    float acc[4][4][4] = {};
    float4 aReg[8];

    // ---- prologue: stage 0 ----
#pragma unroll
    for (int p = 0; p < 8; p++)
        aReg[p] = *(const float4*)(Abase + sRowOff[p * 16 + arow] + acol);
#pragma unroll
    for (int q = 0; q < 4; q++) {
        const int row = brow + q * 32;
        const size_t gb = (size_t)(bn * 128 + row) * 1536 + bseg;
        cp16(smem_u + (uint32_t)(row * ROWB + bseg) + OFF_B, (const char*)wt + gb);
    }
    CP_COMMIT();
    store_a(dynsm, aReg, arow, t);
    CP_WAIT0();
    __syncthreads();

    // ---- main loop ----
    for (int c = 0; c < NCH; c++) {
        const int cur = c & 1;
        const int nxt = cur ^ 1;
        if (c + 1 < NCH) {
            const int kc = (c + 1) * BKC;
#pragma unroll
            for (int p = 0; p < 8; p++)
                aReg[p] = *(const float4*)(Abase + sRowOff[p * 16 + arow] + kc + acol);
            const uint32_t stb = smem_u + nxt * STAGESZ;
#pragma unroll
            for (int q = 0; q < 4; q++) {
                const int row = brow + q * 32;
                const size_t gb = (size_t)(bn * 128 + row) * 1536 + kc * 2 + bseg;
                cp16(stb + (uint32_t)(row * ROWB + bseg) + OFF_B, (const char*)wt + gb);
            }
            CP_COMMIT();
        }

        const uint32_t sb = smem_u + cur * STAGESZ;
#pragma unroll
        for (int ks = 0; ks < 4; ks++) {
            uint32_t ah[4][4], bb[2][4];
#pragma unroll
            for (int mt = 0; mt < 4; mt++)
                LDSM4(ah[mt], sb + OFF_A + aoff + mt * (16 * ROWB) + ks * 32);
#pragma unroll
            for (int n2 = 0; n2 < 2; n2++)
                LDSM4(bb[n2], sb + OFF_B + boff + n2 * (16 * ROWB) + ks * 32);
#pragma unroll
            for (int mt = 0; mt < 4; mt++)
#pragma unroll
                for (int nt = 0; nt < 4; nt++) {
                    float* cc = acc[mt][nt];
                    const int n2 = nt >> 1, no = nt & 1;
                    MMA(cc, ah[mt], bb[n2][no], bb[n2][2 + no]);
                }
        }

        if (c + 1 < NCH) {
            store_a(dynsm + nxt * STAGESZ, aReg, arow, t);
            CP_WAIT0();
        }
        __syncthreads();
    }

    // ---- epilogue: bias add + store (fp32 for ve/te, fp16 for pat/att) ----
    const int r0 = lane >> 2;
    const int cp2 = (lane & 3) * 2;
#pragma unroll
    for (int nt = 0; nt < 4; nt++) {
        const int gcol = bn * 128 + warp_n * 32 + nt * 8 + cp2;
        const float2 bb = *(const float2*)(bias + gcol);
#pragma unroll
        for (int mt = 0; mt < 4; mt++) {
            const int row0 = mrel + warp_m * 64 + mt * 16 + r0;
            const float x0 = acc[mt][nt][0] + bb.x, y0 = acc[mt][nt][1] + bb.y;
            const float x1 = acc[mt][nt][2] + bb.x, y1 = acc[mt][nt][3] + bb.y;
            if (dstf) {
                *(float2*)(dstf + (size_t)row0 * EE + gcol) = make_float2(x0, y0);
                *(float2*)(dstf + (size_t)(row0 + 8) * EE + gcol) = make_float2(x1, y1);
            } else {
                __half2 h0 = __floats2half2_rn(x0, y0);
                __half2 h1 = __floats2half2_rn(x1, y1);
                *(__half2*)(dsth + (size_t)row0 * EE + gcol) = h0;
                *(__half2*)(dsth + (size_t)(row0 + 8) * EE + gcol) = h1;
            }
        }
    }
}

// ---------------- sim v4b: v4 structure + half2 vectorized loads ----------
__global__ __launch_bounds__(256)
void sim_kernel(const __half* __restrict__ pat, const __half* __restrict__ att,
                float* __restrict__ sim)
{
    __shared__ float s_att[AA][EE];
    const int b = blockIdx.x;
    const int t = threadIdx.x;
    const int warp = t >> 5, lane = t & 31;

    // warp w normalizes att row w into SMEM (half2 loads: lane -> pairs)
    {
        const __half2* ar2 = (const __half2*)(att + ((size_t)b * AA + warp) * EE);
        float2 f[4];
        float ss = 0.f;
#pragma unroll
        for (int i = 0; i < 4; i++) {
            f[i] = __half22float2(ar2[lane + 32 * i]);
            ss += f[i].x * f[i].x + f[i].y * f[i].y;
        }
#pragma unroll
        for (int o = 16; o; o >>= 1) ss += __shfl_xor_sync(0xffffffffu, ss, o);
        const float inv = 1.f / fmaxf(sqrtf(ss), 1e-12f);
#pragma unroll
        for (int i = 0; i < 4; i++) {
            const int e = 2 * (lane + 32 * i);
            s_att[warp][e]     = f[i].x * inv;
            s_att[warp][e + 1] = f[i].y * inv;
        }
    }
    __syncthreads();

    // warp handles p = warp, warp+8, ... ; pat row read once via half2
    for (int p = warp; p < Pp; p += 8) {
        const __half2* pr2 = (const __half2*)(pat + ((size_t)b * Pp + p) * EE);
        float2 f[4];
        float ss = 0.f;
#pragma unroll
        for (int i = 0; i < 4; i++) {
            f[i] = __half22float2(pr2[lane + 32 * i]);
            ss += f[i].x * f[i].x + f[i].y * f[i].y;
        }
        float acc[AA] = {};
#pragma unroll
        for (int i = 0; i < 4; i++) {
            const int e = 2 * (lane + 32 * i);
#pragma unroll
            for (int a = 0; a < AA; a++)
                acc[a] += f[i].x * s_att[a][e] + f[i].y * s_att[a][e + 1];
        }
#pragma unroll
        for (int o = 16; o; o >>= 1) ss += __shfl_xor_sync(0xffffffffu, ss, o);
#pragma unroll
        for (int a = 0; a < AA; a++)
#pragma unroll
            for (int o = 16; o; o >>= 1) acc[a] += __shfl_xor_sync(0xffffffffu, acc[a], o);
        if (lane == 0) {
            const float inv = 1.f / fmaxf(sqrtf(ss), 1e-12f);
#pragma unroll
            for (int a = 0; a < AA; a++)
                sim[((size_t)b * AA + a) * Pp + p] = acc[a] * inv;
        }
    }
}

// ---------------- Hungarian v5c: branchless, register u, minimal syncs -----
#define HW 4
__global__ __launch_bounds__(32 * HW)
void hungarian_kernel(const float* __restrict__ simg, float* __restrict__ out)
{
    __shared__ float cost_s[HW][AA][Pp];
    __shared__ int   p_s[HW][Pp + 1];
    __shared__ short way_s[HW][Pp + 1];

    const int w = threadIdx.x >> 5;
    const int lane = threadIdx.x & 31;
    const int b = blockIdx.x * HW + w;
    const float FINF = 1e30f;

    float (*cost)[Pp] = cost_s[w];
    int*   psh = p_s[w];
    short* way = way_s[w];

    for (int idx = lane; idx < AA * Pp; idx += 32)
        cost[idx / Pp][idx % Pp] = -simg[(size_t)b * AA * Pp + idx];

    float total = 0.f;

    for (int round = 0; round < KK; round++) {
        float v[6];
#pragma unroll
        for (int s = 0; s < 6; s++) v[s] = 0.f;
        for (int j = lane; j <= Pp; j += 32) psh[j] = 0;
        float u_own = 0.f;                 // lane r owns u[r] (rows 1..8)
        __syncwarp();

        for (int i = 1; i <= AA; i++) {
            float minv[6];
            unsigned usedm = 0;
            unsigned visited = 0;
#pragma unroll
            for (int s = 0; s < 6; s++) minv[s] = FINF;

            int j0 = 0;
            int i0 = i;                    // conceptual p[0] = i
            while (true) {
                // mark incoming column j0 used (branchless; no-op for j0==0)
                {
                    const int cidx = j0 - 1;
                    const bool own = (j0 != 0) & ((cidx & 31) == lane);
                    usedm |= own ? (1u << (cidx >> 5)) : 0u;
                }
                visited |= (1u << i0);
                const float ui0 = __shfl_sync(0xffffffffu, u_own, i0);
                const float* crow = cost[i0 - 1];

                float best = FINF;
                int bestj = 1 << 20;
#pragma unroll
                for (int s = 0; s < 6; s++) {
                    const int c = s * 32 + lane;
                    const float cur = crow[c] - ui0 - v[s];
                    const bool freecol = !((usedm >> s) & 1);
                    const bool upd = freecol & (cur < minv[s]);
                    if (upd) way[c + 1] = (short)j0;       // predicated STS
                    minv[s] = upd ? cur : minv[s];
                    const float mv = freecol ? minv[s] : FINF;
                    if (mv < best) { best = mv; bestj = c + 1; }
                }
                const uint32_t mykey = fkey(best);
                const uint32_t gkey = redux_min(mykey);
                const float delta = funkey(gkey);

                // u update for visited rows (lane r owns u[r]) — branchless
                u_own += ((visited >> lane) & 1) ? delta : 0.f;
#pragma unroll
                for (int s = 0; s < 6; s++) {
                    const bool usedc = (usedm >> s) & 1;
                    v[s]    -= usedc ? delta : 0.f;
                    minv[s] -= usedc ? 0.f : delta;
                }
                const uint32_t idxc = (mykey == gkey) ? (uint32_t)bestj : 0xFFFFFFFFu;
                const int j1 = (int)redux_min(idxc);   // warp-sync: orders way[] stores
                i0 = psh[j1];                          // next matched row (0 = free col)
                j0 = j1;
                if (i0 == 0) break;
            }
            // redux above is the sync point: way[] writes visible to lane 0;
            // lane 0's psh writes become visible at the next redux before any read.
            if (lane == 0) {
                int jc = j0;
                while (jc) {
                    const int jn = way[jc];
                    psh[jc] = (jn == 0) ? i : psh[jn];   // path root is row i
                    jc = jn;
                }
            }
        }
        __syncwarp();

        // collect matched values + mask
#pragma unroll
        for (int s = 0; s < 6; s++) {
            const int c = s * 32 + lane;
            const int r = psh[c + 1];
            if (r) {
                total += -cost[r - 1][c];
                cost[r - 1][c] = 100.f;
            }
        }
        __syncwarp();
    }

#pragma unroll
    for (int o = 16; o; o >>= 1) total += __shfl_xor_sync(0xffffffffu, total, o);
    if (lane == 0) out[b] = total * (1.f / (KK * AA));
}

// ---------------- launch ----------------
extern "C" void kernel_launch(void* const* d_in, const int* in_sizes, int n_in,
                              void* d_out, int out_size)
{
    const float* vf = (const float*)d_in[0];
    const float* tf = (const float*)d_in[1];
    const float* af = (const float*)d_in[2];
    const float* Wv = (const float*)d_in[4];
    const float* bv = (const float*)d_in[5];
    const float* Wt = (const float*)d_in[6];
    const float* bt = (const float*)d_in[7];
    const float* Wp = (const float*)d_in[8];
    const float* bp = (const float*)d_in[9];
    const float* Wa = (const float*)d_in[10];
    const float* ba = (const float*)d_in[11];

    float* out = (float*)d_out;
    float* ls = out + 2 * Bb * EE;

    __half *gpat, *gatt;
    float *gsim;
    cudaGetSymbolAddress((void**)&gpat, g_pat);
    cudaGetSymbolAddress((void**)&gatt, g_att);
    cudaGetSymbolAddress((void**)&gsim, g_sim);

    cudaFuncSetAttribute(gemm_mma, cudaFuncAttributeMaxDynamicSharedMemorySize, DYNSZ);

    wsplit_kernel<<<dim3(24, 8, 4), dim3(32, 8)>>>(Wv, Wt, Wp, Wa);
    gemm_mma<<<dim3(2, MTILES), 256, DYNSZ>>>(vf, tf, af, bv, bt, bp, ba, out);
    sim_kernel<<<Bb, 256>>>(gpat, gatt, gsim);
    hungarian_kernel<<<Bb / HW, 32 * HW>>>(gsim, ls);
}

// round 16
// speedup vs baseline: 1.1587x; 1.0446x over previous
#include <cuda_runtime.h>
#include <cuda_bf16.h>
#include <cuda_fp16.h>
#include <cstdint>

// ---------------- constants ----------------
#define Bb   256
#define Pp   192
#define DD   768
#define EE   256
#define AA   8
#define KK   4

#define M_TOTAL   51712          // 256(ve) + 256(te) + 49152(pat) + 2048(att)
#define SEG1      256
#define SEG2      512
#define SEG3      49664
#define MTILES    404            // M_TOTAL / 128
#define BKC       64             // K per chunk (fp16 elems)
#define NCH       12             // 768 / 64

// SMEM: 2 operands (A, B), each 128 rows x 144 bytes, double buffered
#define ROWB    144
#define OPSZ    (128 * ROWB)     // 18432
#define OFF_A   0
#define OFF_B   (OPSZ)
#define STAGESZ (2 * OPSZ)       // 36864
#define DYNSZ   (2 * STAGESZ)    // 73728

// ---------------- scratch ----------------
__device__ __half g_pat[(size_t)Bb * Pp * EE];  // unnormalized patch embed (fp16)
__device__ __half g_att[(size_t)Bb * AA * EE];  // unnormalized att embed (fp16)
__device__ __half g_wt[4][256 * 768];           // W^T fp16, [N][K]

// ---------------- PTX helpers ----------------
static __device__ __forceinline__ uint32_t smem_u32(const void* p) {
    uint32_t a;
    asm("{ .reg .u64 t; cvta.to.shared.u64 t, %1; cvt.u32.u64 %0, t; }"
        : "=r"(a) : "l"(p));
    return a;
}

#define LDSM4(r, addr) \
    asm volatile("ldmatrix.sync.aligned.m8n8.x4.shared.b16 {%0,%1,%2,%3}, [%4];" \
        : "=r"((r)[0]), "=r"((r)[1]), "=r"((r)[2]), "=r"((r)[3]) : "r"(addr))

#define MMA(c, a, b0, b1) \
    asm volatile("mma.sync.aligned.m16n8k16.row.col.f32.f16.f16.f32 " \
        "{%0,%1,%2,%3}, {%4,%5,%6,%7}, {%8,%9}, {%0,%1,%2,%3};" \
        : "+f"((c)[0]), "+f"((c)[1]), "+f"((c)[2]), "+f"((c)[3]) \
        : "r"((a)[0]), "r"((a)[1]), "r"((a)[2]), "r"((a)[3]), "r"(b0), "r"(b1))

static __device__ __forceinline__ void cp16(uint32_t s, const void* g) {
    asm volatile("cp.async.cg.shared.global [%0], [%1], 16;" :: "r"(s), "l"(g));
}
#define CP_COMMIT() asm volatile("cp.async.commit_group;" ::: "memory")
#define CP_WAIT0()  asm volatile("cp.async.wait_group 0;" ::: "memory")

// redux with memory clobber: warp-synchronizing + orders shared-mem writes
static __device__ __forceinline__ uint32_t redux_min(uint32_t v) {
    uint32_t d;
    asm volatile("redux.sync.min.u32 %0, %1, 0xFFFFFFFF;" : "=r"(d) : "r"(v) : "memory");
    return d;
}
static __device__ __forceinline__ uint32_t fkey(float f) {
    const uint32_t u = __float_as_uint(f);
    return (u & 0x80000000u) ? ~u : (u | 0x80000000u);
}
static __device__ __forceinline__ float funkey(uint32_t k) {
    const uint32_t u = (k & 0x80000000u) ? (k ^ 0x80000000u) : ~k;
    return __uint_as_float(u);
}

// ---------------- W transpose + fp16 convert ----------------
__global__ void wsplit_kernel(const float* __restrict__ W0, const float* __restrict__ W1,
                              const float* __restrict__ W2, const float* __restrict__ W3)
{
    const int z = blockIdx.z;
    const float* W = (z == 0) ? W0 : (z == 1) ? W1 : (z == 2) ? W2 : W3;
    __shared__ float tile[32][33];
    const int tx = threadIdx.x, ty = threadIdx.y;
    const int k0 = blockIdx.x * 32, n0 = blockIdx.y * 32;
#pragma unroll
    for (int i = 0; i < 4; i++)
        tile[ty + 8 * i][tx] = W[(size_t)(k0 + ty + 8 * i) * 256 + n0 + tx];
    __syncthreads();
#pragma unroll
    for (int i = 0; i < 4; i++) {
        const float v = tile[tx][ty + 8 * i];
        g_wt[z][(size_t)(n0 + ty + 8 * i) * 768 + k0 + tx] = __float2half(v);
    }
}

// ---------------- A convert+store helper (fp32 -> fp16) ----------------
static __device__ __forceinline__ void store_a(char* st, const float4* aReg,
                                               int arow, int t)
{
#pragma unroll
    for (int p = 0; p < 8; p++) {
        const float4 v = aReg[p];
        __half2 hp0 = __floats2half2_rn(v.x, v.y);
        __half2 hp1 = __floats2half2_rn(v.z, v.w);
        uint2 hv;
        hv.x = *(uint32_t*)&hp0; hv.y = *(uint32_t*)&hp1;
        const int byo = (p * 16 + arow) * ROWB + (t & 15) * 8;
        *(uint2*)(st + OFF_A + byo) = hv;
    }
}

// ---------------- fused HMMA GEMM: C[m,256] = A[m,768] @ W + bias ----------
__global__ __launch_bounds__(256, 2)
void gemm_mma(const float* __restrict__ vf, const float* __restrict__ tf,
              const float* __restrict__ af,
              const float* __restrict__ bv, const float* __restrict__ bt,
              const float* __restrict__ bp, const float* __restrict__ ba,
              float* __restrict__ out)
{
    extern __shared__ char dynsm[];
    __shared__ int sRowOff[128];

    const int t = threadIdx.x;
    const int warp = t >> 5;
    const int lane = t & 31;
    const int m0 = blockIdx.y * 128;
    const int bn = blockIdx.x;           // 0 or 1 (N halves) — adjacent CTAs share A via L2

    const int seg = (m0 < SEG1) ? 0 : (m0 < SEG2) ? 1 : (m0 < SEG3) ? 2 : 3;
    const float* Abase = (seg == 0 || seg == 2) ? vf : (seg == 1 ? tf : af);
    const float* bias = (seg == 0) ? bv : (seg == 1) ? bt : (seg == 2) ? bp : ba;
    const __half* wt = g_wt[seg];

    float* dstf = nullptr;
    __half* dsth = nullptr;
    int mrel;
    if (seg == 0)      { dstf = out;            mrel = m0; }
    else if (seg == 1) { dstf = out + Bb * EE;  mrel = m0 - SEG1; }
    else if (seg == 2) { dsth = g_pat;          mrel = m0 - SEG2; }
    else               { dsth = g_att;          mrel = m0 - SEG3; }

    if (t < 128) {
        const int m = m0 + t;
        int off;
        if (m < SEG1)        off = m * (193 * 768);
        else if (m < SEG2)   off = (m - SEG1) * 768;
        else if (m < SEG3) { const int mm = m - SEG2;
                             off = ((mm / 192) * 193 + 1 + (mm % 192)) * 768; }
        else                 off = (m - SEG3) * 768;
        sRowOff[t] = off;
    }
    __syncthreads();

    const uint32_t smem_u = smem_u32(dynsm);
    const int warp_m = warp & 1;          // 2 m-warps (64 rows each)
    const int warp_n = warp >> 1;         // 4 n-warps (32 cols each)
    const int g = lane >> 3, lr = lane & 7;
    const uint32_t aoff = (uint32_t)((warp_m * 64 + (g & 1) * 8 + lr) * ROWB + (g >> 1) * 16);
    const uint32_t boff = (uint32_t)((warp_n * 32 + (g & 1) * 8 + lr) * ROWB + (g >> 1) * 16);

    const int arow = t >> 4;              // 0..15, + 16*pass
    const int acol = (t & 15) * 4;        // floats
    const int brow = t >> 3;              // 0..31, + 32*pass
    const int bseg = (t & 7) * 16;        // bytes within 128B row

    float acc[4][4][4] = {};
    float4 aReg[8];

    // ---- prologue: stage 0 ----
#pragma unroll
    for (int p = 0; p < 8; p++)
        aReg[p] = *(const float4*)(Abase + sRowOff[p * 16 + arow] + acol);
#pragma unroll
    for (int q = 0; q < 4; q++) {
        const int row = brow + q * 32;
        const size_t gb = (size_t)(bn * 128 + row) * 1536 + bseg;
        cp16(smem_u + (uint32_t)(row * ROWB + bseg) + OFF_B, (const char*)wt + gb);
    }
    CP_COMMIT();
    store_a(dynsm, aReg, arow, t);
    CP_WAIT0();
    __syncthreads();

    // ---- main loop ----
    for (int c = 0; c < NCH; c++) {
        const int cur = c & 1;
        const int nxt = cur ^ 1;
        if (c + 1 < NCH) {
            const int kc = (c + 1) * BKC;
#pragma unroll
            for (int p = 0; p < 8; p++)
                aReg[p] = *(const float4*)(Abase + sRowOff[p * 16 + arow] + kc + acol);
            const uint32_t stb = smem_u + nxt * STAGESZ;
#pragma unroll
            for (int q = 0; q < 4; q++) {
                const int row = brow + q * 32;
                const size_t gb = (size_t)(bn * 128 + row) * 1536 + kc * 2 + bseg;
                cp16(stb + (uint32_t)(row * ROWB + bseg) + OFF_B, (const char*)wt + gb);
            }
            CP_COMMIT();
        }

        const uint32_t sb = smem_u + cur * STAGESZ;
#pragma unroll
        for (int ks = 0; ks < 4; ks++) {
            uint32_t ah[4][4], bb[2][4];
#pragma unroll
            for (int mt = 0; mt < 4; mt++)
                LDSM4(ah[mt], sb + OFF_A + aoff + mt * (16 * ROWB) + ks * 32);
#pragma unroll
            for (int n2 = 0; n2 < 2; n2++)
                LDSM4(bb[n2], sb + OFF_B + boff + n2 * (16 * ROWB) + ks * 32);
#pragma unroll
            for (int mt = 0; mt < 4; mt++)
#pragma unroll
                for (int nt = 0; nt < 4; nt++) {
                    float* cc = acc[mt][nt];
                    const int n2 = nt >> 1, no = nt & 1;
                    MMA(cc, ah[mt], bb[n2][no], bb[n2][2 + no]);
                }
        }

        if (c + 1 < NCH) {
            store_a(dynsm + nxt * STAGESZ, aReg, arow, t);
            CP_WAIT0();
        }
        __syncthreads();
    }

    // ---- epilogue: bias add + store (fp32 for ve/te, fp16 for pat/att) ----
    const int r0 = lane >> 2;
    const int cp2 = (lane & 3) * 2;
#pragma unroll
    for (int nt = 0; nt < 4; nt++) {
        const int gcol = bn * 128 + warp_n * 32 + nt * 8 + cp2;
        const float2 bb = *(const float2*)(bias + gcol);
#pragma unroll
        for (int mt = 0; mt < 4; mt++) {
            const int row0 = mrel + warp_m * 64 + mt * 16 + r0;
            const float x0 = acc[mt][nt][0] + bb.x, y0 = acc[mt][nt][1] + bb.y;
            const float x1 = acc[mt][nt][2] + bb.x, y1 = acc[mt][nt][3] + bb.y;
            if (dstf) {
                *(float2*)(dstf + (size_t)row0 * EE + gcol) = make_float2(x0, y0);
                *(float2*)(dstf + (size_t)(row0 + 8) * EE + gcol) = make_float2(x1, y1);
            } else {
                __half2 h0 = __floats2half2_rn(x0, y0);
                __half2 h1 = __floats2half2_rn(x1, y1);
                *(__half2*)(dsth + (size_t)row0 * EE + gcol) = h0;
                *(__half2*)(dsth + (size_t)(row0 + 8) * EE + gcol) = h1;
            }
        }
    }
}

// ---------------- fused sim + Hungarian (small SMEM, 1 block/batch) --------
__global__ __launch_bounds__(256, 1)
void simhung_kernel(const __half* __restrict__ pat, const __half* __restrict__ att,
                    float* __restrict__ out)
{
    __shared__ float s_att[AA][EE];      // 8 KB
    __shared__ float cost[AA][Pp];       // 6 KB  (= -sim)
    __shared__ int   psh[Pp + 1];
    __shared__ short way[Pp + 1];

    const int b = blockIdx.x;
    const int t = threadIdx.x;
    const int warp = t >> 5, lane = t & 31;
    const float FINF = 1e30f;

    // ---------- sim phase (all 8 warps; sim v4b) ----------
    {
        const __half2* ar2 = (const __half2*)(att + ((size_t)b * AA + warp) * EE);
        float2 f[4];
        float ss = 0.f;
#pragma unroll
        for (int i = 0; i < 4; i++) {
            f[i] = __half22float2(ar2[lane + 32 * i]);
            ss += f[i].x * f[i].x + f[i].y * f[i].y;
        }
#pragma unroll
        for (int o = 16; o; o >>= 1) ss += __shfl_xor_sync(0xffffffffu, ss, o);
        const float inv = 1.f / fmaxf(sqrtf(ss), 1e-12f);
#pragma unroll
        for (int i = 0; i < 4; i++) {
            const int e = 2 * (lane + 32 * i);
            s_att[warp][e]     = f[i].x * inv;
            s_att[warp][e + 1] = f[i].y * inv;
        }
    }
    __syncthreads();

    for (int p = warp; p < Pp; p += 8) {
        const __half2* pr2 = (const __half2*)(pat + ((size_t)b * Pp + p) * EE);
        float2 f[4];
        float ss = 0.f;
#pragma unroll
        for (int i = 0; i < 4; i++) {
            f[i] = __half22float2(pr2[lane + 32 * i]);
            ss += f[i].x * f[i].x + f[i].y * f[i].y;
        }
        float acc[AA] = {};
#pragma unroll
        for (int i = 0; i < 4; i++) {
            const int e = 2 * (lane + 32 * i);
#pragma unroll
            for (int a = 0; a < AA; a++)
                acc[a] += f[i].x * s_att[a][e] + f[i].y * s_att[a][e + 1];
        }
#pragma unroll
        for (int o = 16; o; o >>= 1) ss += __shfl_xor_sync(0xffffffffu, ss, o);
#pragma unroll
        for (int a = 0; a < AA; a++)
#pragma unroll
            for (int o = 16; o; o >>= 1) acc[a] += __shfl_xor_sync(0xffffffffu, acc[a], o);
        if (lane == 0) {
            const float inv = 1.f / fmaxf(sqrtf(ss), 1e-12f);
#pragma unroll
            for (int a = 0; a < AA; a++)
                cost[a][p] = -(acc[a] * inv);
        }
    }
    __syncthreads();

    if (warp != 0) return;

    // ---------- Hungarian phase (warp 0; v5c) ----------
    float total = 0.f;

    for (int round = 0; round < KK; round++) {
        float v[6];
#pragma unroll
        for (int s = 0; s < 6; s++) v[s] = 0.f;
        for (int j = lane; j <= Pp; j += 32) psh[j] = 0;
        float u_own = 0.f;                 // lane r owns u[r] (rows 1..8)
        __syncwarp();

        for (int i = 1; i <= AA; i++) {
            float minv[6];
            unsigned usedm = 0;
            unsigned visited = 0;
#pragma unroll
            for (int s = 0; s < 6; s++) minv[s] = FINF;

            int j0 = 0;
            int i0 = i;                    // conceptual p[0] = i
            while (true) {
                // mark incoming column j0 used (branchless; no-op for j0==0)
                {
                    const int cidx = j0 - 1;
                    const bool own = (j0 != 0) & ((cidx & 31) == lane);
                    usedm |= own ? (1u << (cidx >> 5)) : 0u;
                }
                visited |= (1u << i0);
                const float ui0 = __shfl_sync(0xffffffffu, u_own, i0);
                const float* crow = cost[i0 - 1];

                float best = FINF;
                int bestj = 1 << 20;
#pragma unroll
                for (int s = 0; s < 6; s++) {
                    const int c = s * 32 + lane;
                    const float cur = crow[c] - ui0 - v[s];
                    const bool freecol = !((usedm >> s) & 1);
                    const bool upd = freecol & (cur < minv[s]);
                    if (upd) way[c + 1] = (short)j0;       // predicated STS
                    minv[s] = upd ? cur : minv[s];
                    const float mv = freecol ? minv[s] : FINF;
                    if (mv < best) { best = mv; bestj = c + 1; }
                }
                const uint32_t mykey = fkey(best);
                const uint32_t gkey = redux_min(mykey);
                const float delta = funkey(gkey);

                // u update for visited rows (lane r owns u[r]) — branchless
                u_own += ((visited >> lane) & 1) ? delta : 0.f;
#pragma unroll
                for (int s = 0; s < 6; s++) {
                    const bool usedc = (usedm >> s) & 1;
                    v[s]    -= usedc ? delta : 0.f;
                    minv[s] -= usedc ? 0.f : delta;
                }
                const uint32_t idxc = (mykey == gkey) ? (uint32_t)bestj : 0xFFFFFFFFu;
                const int j1 = (int)redux_min(idxc);   // warp-sync: orders way[] stores
                i0 = psh[j1];                          // next matched row (0 = free col)
                j0 = j1;
                if (i0 == 0) break;
            }
            // redux above is the sync point: way[] writes visible to lane 0;
            // lane 0's psh writes become visible at the next redux before any read.
            if (lane == 0) {
                int jc = j0;
                while (jc) {
                    const int jn = way[jc];
                    psh[jc] = (jn == 0) ? i : psh[jn];   // path root is row i
                    jc = jn;
                }
            }
        }
        __syncwarp();

        // collect matched values + mask
#pragma unroll
        for (int s = 0; s < 6; s++) {
            const int c = s * 32 + lane;
            const int r = psh[c + 1];
            if (r) {
                total += -cost[r - 1][c];
                cost[r - 1][c] = 100.f;
            }
        }
        __syncwarp();
    }

#pragma unroll
    for (int o = 16; o; o >>= 1) total += __shfl_xor_sync(0xffffffffu, total, o);
    if (lane == 0) out[b] = total * (1.f / (KK * AA));
}

// ---------------- launch ----------------
extern "C" void kernel_launch(void* const* d_in, const int* in_sizes, int n_in,
                              void* d_out, int out_size)
{
    const float* vf = (const float*)d_in[0];
    const float* tf = (const float*)d_in[1];
    const float* af = (const float*)d_in[2];
    const float* Wv = (const float*)d_in[4];
    const float* bv = (const float*)d_in[5];
    const float* Wt = (const float*)d_in[6];
    const float* bt = (const float*)d_in[7];
    const float* Wp = (const float*)d_in[8];
    const float* bp = (const float*)d_in[9];
    const float* Wa = (const float*)d_in[10];
    const float* ba = (const float*)d_in[11];

    float* out = (float*)d_out;
    float* ls = out + 2 * Bb * EE;

    __half *gpat, *gatt;
    cudaGetSymbolAddress((void**)&gpat, g_pat);
    cudaGetSymbolAddress((void**)&gatt, g_att);

    cudaFuncSetAttribute(gemm_mma, cudaFuncAttributeMaxDynamicSharedMemorySize, DYNSZ);

    wsplit_kernel<<<dim3(24, 8, 4), dim3(32, 8)>>>(Wv, Wt, Wp, Wa);
    gemm_mma<<<dim3(2, MTILES), 256, DYNSZ>>>(vf, tf, af, bv, bt, bp, ba, out);
    simhung_kernel<<<Bb, 256>>>(gpat, gatt, ls);
}